// round 3
// baseline (speedup 1.0000x reference)
#include <cuda_runtime.h>
#include <math.h>

#define T_TOKENS 16384
#define N_EXP    256
#define HID      7168
#define NGROUP   8
#define TOPKG    4
#define TOPK     8

#define SLICES   8
#define KSLICE   (HID / SLICES)   // 896

// scratch: 8 x 16.8 MB fp32 partials + 16.8 MB logits (static device alloc is allowed)
__device__ float g_partial[(size_t)SLICES * T_TOKENS * N_EXP];
__device__ float g_logits[(size_t)T_TOKENS * N_EXP];

typedef unsigned long long ull;

// ---------------------------------------------------------------------------
// packed fp32x2 helpers
// ---------------------------------------------------------------------------
__device__ __forceinline__ ull pack2(float x, float y) {
    ull r; asm("mov.b64 %0, {%1, %2};" : "=l"(r) : "f"(x), "f"(y)); return r;
}
__device__ __forceinline__ void unpack2(ull v, float& x, float& y) {
    asm("mov.b64 {%0, %1}, %2;" : "=f"(x), "=f"(y) : "l"(v));
}
__device__ __forceinline__ void fma2(ull& d, ull a, ull b) {
    asm("fma.rn.f32x2 %0, %1, %2, %0;" : "+l"(d) : "l"(a), "l"(b));
}
__device__ __forceinline__ ull add2(ull a, ull b) {
    ull r; asm("add.rn.f32x2 %0, %1, %2;" : "=l"(r) : "l"(a), "l"(b)); return r;
}

// ---------------------------------------------------------------------------
// Phase 1: split-K router GEMM.  partial[z][t,e] = sum_{k in slice z} A[t,k]W[e,k]
// BM=64, BN=128, BK=8, 256 threads, 4x8 microtile, 32-k chunked accumulation.
// ---------------------------------------------------------------------------
#define BM 64
#define BN 128
#define BK 8

__global__ __launch_bounds__(256, 2) void router_gemm(
    const float* __restrict__ A, const float* __restrict__ W)
{
    __shared__ float As[BK][BM + 4];
    __shared__ float Ws[BK][BN + 4];

    const int tid  = threadIdx.x;
    const int tx   = tid & 15;        // expert microtile col 0..15 (8 cols each)
    const int ty   = tid >> 4;        // token microtile row 0..15 (4 rows each)
    const int arow = tid >> 2;        // 0..63
    const int acol = (tid & 3) * 2;   // 0,2,4,6
    const int wrow = tid >> 1;        // 0..127
    const int wcol = (tid & 1) * 4;   // 0,4

    const int kbase = blockIdx.z * KSLICE;
    const float* Ap = A + (size_t)(blockIdx.x * BM + arow) * HID + kbase + acol;
    const float* Wp = W + (size_t)(blockIdx.y * BN + wrow) * HID + kbase + wcol;

    ull sum[4][4];
#pragma unroll
    for (int i = 0; i < 4; ++i)
#pragma unroll
        for (int j = 0; j < 4; ++j) sum[i][j] = 0ull;

    // 896 k = 28 chunks of 32 k = 28 x (4 x BK)
    for (int c = 0; c < KSLICE / 32; ++c) {
        ull chk[4][4];
#pragma unroll
        for (int i = 0; i < 4; ++i)
#pragma unroll
            for (int j = 0; j < 4; ++j) chk[i][j] = 0ull;

#pragma unroll
        for (int kb = 0; kb < 4; ++kb) {
            float2 av = *(const float2*)Ap;
            float4 wv = *(const float4*)Wp;
            Ap += BK; Wp += BK;
            __syncthreads();
            As[acol + 0][arow] = av.x; As[acol + 1][arow] = av.y;
            Ws[wcol + 0][wrow] = wv.x; Ws[wcol + 1][wrow] = wv.y;
            Ws[wcol + 2][wrow] = wv.z; Ws[wcol + 3][wrow] = wv.w;
            __syncthreads();

#pragma unroll
            for (int k = 0; k < BK; ++k) {
                float4 a  = *(const float4*)&As[k][ty * 4];
                float4 b0 = *(const float4*)&Ws[k][tx * 8];
                float4 b1 = *(const float4*)&Ws[k][tx * 8 + 4];
                ull bp[4];
                bp[0] = pack2(b0.x, b0.y); bp[1] = pack2(b0.z, b0.w);
                bp[2] = pack2(b1.x, b1.y); bp[3] = pack2(b1.z, b1.w);
                float aa[4] = {a.x, a.y, a.z, a.w};
#pragma unroll
                for (int i = 0; i < 4; ++i) {
                    ull ap = pack2(aa[i], aa[i]);
#pragma unroll
                    for (int j = 0; j < 4; ++j) fma2(chk[i][j], ap, bp[j]);
                }
            }
        }
        // fold chunk into slice sum (28 small-magnitude adds)
#pragma unroll
        for (int i = 0; i < 4; ++i)
#pragma unroll
            for (int j = 0; j < 4; ++j) sum[i][j] = add2(sum[i][j], chk[i][j]);
    }

    float* base = g_partial + (size_t)blockIdx.z * T_TOKENS * N_EXP;
#pragma unroll
    for (int i = 0; i < 4; ++i) {
        float* crow = base + (size_t)(blockIdx.x * BM + ty * 4 + i) * N_EXP
                    + blockIdx.y * BN + tx * 8;
#pragma unroll
        for (int j = 0; j < 4; ++j) {
            float lo, hi;
            unpack2(sum[i][j], lo, hi);
            crow[2 * j]     = lo;
            crow[2 * j + 1] = hi;
        }
    }
}

// ---------------------------------------------------------------------------
// Phase 1b: fp64 reduction of the 8 slice partials -> logits (exact)
// ---------------------------------------------------------------------------
__global__ __launch_bounds__(256) void reduce_logits() {
    const size_t idx = (size_t)blockIdx.x * 256 + threadIdx.x;
    double s = 0.0;
#pragma unroll
    for (int z = 0; z < SLICES; ++z)
        s += (double)g_partial[(size_t)z * T_TOKENS * N_EXP + idx];
    g_logits[idx] = (float)s;
}

// ---------------------------------------------------------------------------
// Phase 2: grouped top-k routing. One warp per token, 8 warps per block.
// Lane l owns experts [l*8, l*8+8)  =>  group g = lanes [4g, 4g+4)
// ---------------------------------------------------------------------------
__global__ __launch_bounds__(256) void topk_kernel(
    const float* __restrict__ bias,
    float* __restrict__ out_idx,
    float* __restrict__ out_w)
{
    __shared__ float bsh[N_EXP];
    __shared__ float s_sh[8][N_EXP];   // sigmoid cache per warp

    const int tid  = threadIdx.x;
    const int warp = tid >> 5;
    const int lane = tid & 31;
    const unsigned FULL = 0xFFFFFFFFu;

    if (tid < N_EXP) bsh[tid] = bias[tid];
    __syncthreads();

    const int token = blockIdx.x * 8 + warp;
    const float* lg = g_logits + (size_t)token * N_EXP + lane * 8;

    float c[8];
#pragma unroll
    for (int j = 0; j < 8; ++j) {
        float x = lg[j];
        float sg = 1.0f / (1.0f + expf(-x));
        c[j] = sg + bsh[lane * 8 + j];
        s_sh[warp][lane * 8 + j] = sg;
    }
    __syncwarp();

    // per-lane top-2 of its 8 corrected scores
    float m1 = -INFINITY, m2 = -INFINITY;
#pragma unroll
    for (int j = 0; j < 8; ++j) {
        float v = c[j];
        if (v > m1) { m2 = m1; m1 = v; }
        else if (v > m2) { m2 = v; }
    }
    // merge top-2 across the 4 lanes of the group (butterfly, width 4)
#pragma unroll
    for (int off = 2; off >= 1; off >>= 1) {
        float o1 = __shfl_xor_sync(FULL, m1, off);
        float o2 = __shfl_xor_sync(FULL, m2, off);
        if (o1 > m1) { m2 = fmaxf(m1, o2); m1 = o1; }
        else         { m2 = fmaxf(m2, o1); }
    }
    float gsum = m1 + m2;   // identical on all 4 lanes of the group

    // broadcast all 8 group scores to every lane
    float gs[NGROUP];
#pragma unroll
    for (int g = 0; g < NGROUP; ++g) gs[g] = __shfl_sync(FULL, gsum, g * 4);

    // top-4 groups, jax tie-break (lower index wins on equal values)
    const int myg = lane >> 2;
    const float mys = gs[myg];
    int rank = 0;
#pragma unroll
    for (int g = 0; g < NGROUP; ++g)
        rank += (gs[g] > mys) || (gs[g] == mys && g < myg);
    const bool sel = (rank < TOPKG);

    // masked scores: exactly 0.0f outside selected groups (matches reference)
    float mc[8];
#pragma unroll
    for (int j = 0; j < 8; ++j) mc[j] = sel ? c[j] : 0.0f;

    // iterative top-8 with stable jax.lax.top_k ordering
    float wsum = 0.0f;
    int   myidx = 0;
    float myw   = 0.0f;
#pragma unroll
    for (int t = 0; t < TOPK; ++t) {
        float bv = -INFINITY;
        int   bi = N_EXP;
#pragma unroll
        for (int j = 0; j < 8; ++j) {
            if (mc[j] > bv) { bv = mc[j]; bi = lane * 8 + j; }  // strict > => lowest idx kept
        }
#pragma unroll
        for (int off = 16; off >= 1; off >>= 1) {
            float ov = __shfl_xor_sync(FULL, bv, off);
            int   oi = __shfl_xor_sync(FULL, bi, off);
            if (ov > bv || (ov == bv && oi < bi)) { bv = ov; bi = oi; }
        }
        // all lanes agree on (bv, bi); weight = sigmoid score at bi
        float sv = s_sh[warp][bi];
        wsum += sv;
        if (lane == t) { myidx = bi; myw = sv; }
        // remove from owning lane
        if ((bi >> 3) == lane) {
            int jj = bi & 7;
#pragma unroll
            for (int j = 0; j < 8; ++j)
                if (j == jj) mc[j] = -INFINITY;
        }
    }

    const float scale = 2.5f / (wsum + 1e-20f);
    if (lane < TOPK) {
        out_idx[(size_t)token * TOPK + lane] = (float)myidx;
        out_w  [(size_t)token * TOPK + lane] = myw * scale;
    }
}

// ---------------------------------------------------------------------------
extern "C" void kernel_launch(void* const* d_in, const int* in_sizes, int n_in,
                              void* d_out, int out_size) {
    const float* hidden = (const float*)d_in[0];   // [16384, 7168]
    const float* weight = (const float*)d_in[1];   // [256, 7168]
    const float* bias   = (const float*)d_in[2];   // [256]
    float* out = (float*)d_out;                    // [indices | weights], fp32

    dim3 g1(T_TOKENS / BM, N_EXP / BN, SLICES);
    router_gemm<<<g1, 256>>>(hidden, weight);
    reduce_logits<<<(T_TOKENS * N_EXP) / 256, 256>>>();
    topk_kernel<<<T_TOKENS / 8, 256>>>(bias, out, out + (size_t)T_TOKENS * TOPK);
}

// round 7
// speedup vs baseline: 2.4820x; 2.4820x over previous
#include <cuda_runtime.h>
#include <cuda_fp16.h>
#include <math.h>

#define T_TOKENS 16384
#define N_EXP    256
#define HID      7168
#define NGROUP   8
#define TOPKG    4
#define TOPK     8

#define BLK_M    128
#define BLK_N    64
#define BK       32
#define NSTAGES  224           // HID / BK
#define STAGE_BYTES 24576      // Ah 8192 | Am 8192 | Bh 4096 | Bm 4096
#define SMEM_TOTAL 49152

typedef unsigned int u32;

// static device scratch (allowed)
__device__ __half g_Wh[(size_t)HID * N_EXP];     // W transposed, high limb  [k][n]
__device__ __half g_Wm[(size_t)HID * N_EXP];     // W transposed, low  limb  [k][n]
__device__ float  g_logits[(size_t)T_TOKENS * N_EXP];

// ---------------------------------------------------------------------------
__device__ __forceinline__ u32 smem_u32(const void* p) {
    u32 r;
    asm("{ .reg .u64 t; cvta.to.shared.u64 t, %1; cvt.u32.u64 %0, t; }" : "=r"(r) : "l"(p));
    return r;
}

__device__ __forceinline__ void ldmA(u32* r, u32 addr) {
    asm volatile("ldmatrix.sync.aligned.m8n8.x4.shared.b16 {%0,%1,%2,%3}, [%4];"
                 : "=r"(r[0]), "=r"(r[1]), "=r"(r[2]), "=r"(r[3]) : "r"(addr));
}
__device__ __forceinline__ void ldmBT(u32* r, u32 addr) {
    asm volatile("ldmatrix.sync.aligned.m8n8.x4.trans.shared.b16 {%0,%1,%2,%3}, [%4];"
                 : "=r"(r[0]), "=r"(r[1]), "=r"(r[2]), "=r"(r[3]) : "r"(addr));
}
__device__ __forceinline__ void mma16816(float* c, const u32* a, const u32* b) {
    asm volatile(
        "mma.sync.aligned.m16n8k16.row.col.f32.f16.f16.f32 "
        "{%0,%1,%2,%3}, {%4,%5,%6,%7}, {%8,%9}, {%0,%1,%2,%3};"
        : "+f"(c[0]), "+f"(c[1]), "+f"(c[2]), "+f"(c[3])
        : "r"(a[0]), "r"(a[1]), "r"(a[2]), "r"(a[3]), "r"(b[0]), "r"(b[1]));
}
__device__ __forceinline__ void cp16(u32 dst, const void* src) {
    asm volatile("cp.async.cg.shared.global [%0], [%1], 16;" :: "r"(dst), "l"(src) : "memory");
}

// split 16 fp32 -> 8x u32 high-limb pairs + 8x u32 low-limb pairs
__device__ __forceinline__ void split16(const float4* v, u32* H, u32* M) {
    const float* x = (const float*)v;
#pragma unroll
    for (int i = 0; i < 8; ++i) {
        float a = x[2 * i], b = x[2 * i + 1];
        __half ha = __float2half_rn(a), hb = __float2half_rn(b);
        float ma = a - __half2float(ha);
        float mb = b - __half2float(hb);
        __half2 hh = __halves2half2(ha, hb);
        __half2 mm = __floats2half2_rn(ma, mb);
        H[i] = *(u32*)&hh;
        M[i] = *(u32*)&mm;
    }
}

// ---------------------------------------------------------------------------
// Phase 0: W -> transposed fp16 limb arrays Wt[k][n]
// ---------------------------------------------------------------------------
__global__ __launch_bounds__(256) void w_convert(const float* __restrict__ W) {
    const int k = blockIdx.x;        // 0..7167
    const int e = threadIdx.x;       // 0..255
    float x = W[(size_t)e * HID + k];
    __half h = __float2half_rn(x);
    __half m = __float2half_rn(x - __half2float(h));
    g_Wh[(size_t)k * N_EXP + e] = h;
    g_Wm[(size_t)k * N_EXP + e] = m;
}

// ---------------------------------------------------------------------------
// Phase 1: fp16x2-limb HMMA GEMM.  logits[t,e] = sum_k A[t,k] W[e,k]
// CTA 128x64, 8 warps (4m x 2n), warp 32x32, BK=32, double buffered.
// Terms: hh (+ hm + mh); two-level accumulation (fold every 16 stages).
// ---------------------------------------------------------------------------
__global__ __launch_bounds__(256, 1) void router_hmma(const float* __restrict__ A) {
    extern __shared__ char smem[];
    const u32 sbase = smem_u32(smem);
    const int tid = threadIdx.x, lane = tid & 31, wid = tid >> 5;
    const int wm = wid & 3, wn = wid >> 2;

    float mast[2][4][4], chk[2][4][4];
#pragma unroll
    for (int i = 0; i < 2; ++i)
#pragma unroll
        for (int j = 0; j < 4; ++j)
#pragma unroll
            for (int q = 0; q < 4; ++q) { mast[i][j][q] = 0.f; chk[i][j][q] = 0.f; }

    // A staging: thread -> (row am, 16-float half ah)
    const int am = tid >> 1;
    const int ah = tid & 1;
    const float* Aptr = A + (size_t)(blockIdx.x * BLK_M + am) * HID + ah * 16;
    const u32 asts0 = (u32)am * 64 + (u32)((((ah * 2 + 0) ^ (am & 3))) * 16);
    const u32 asts1 = (u32)am * 64 + (u32)((((ah * 2 + 1) ^ (am & 3))) * 16);

    // B staging: thread -> (k row bk, 16B chunk bnc)
    const int bk = tid >> 3;
    const int bnc = tid & 7;
    const int n0 = blockIdx.y * BLK_N;
    const __half* WhP = g_Wh + (size_t)bk * N_EXP + n0 + bnc * 8;
    const __half* WmP = g_Wm + (size_t)bk * N_EXP + n0 + bnc * 8;
    const u32 bswz = (u32)bk * 128 + (u32)((bnc ^ (bk & 7)) * 16);
    const size_t wstride = (size_t)BK * N_EXP;   // halves per stage

    // ---- prologue: stage 0 ----
    float4 ar[4];
    {
        cp16(sbase + 16384 + bswz, WhP);
        cp16(sbase + 20480 + bswz, WmP);
        asm volatile("cp.async.commit_group;" ::: "memory");
#pragma unroll
        for (int i = 0; i < 4; ++i) ar[i] = *(const float4*)(Aptr + i * 4);
        u32 H[8], M[8];
        split16(ar, H, M);
        *(uint4*)(smem + asts0) = make_uint4(H[0], H[1], H[2], H[3]);
        *(uint4*)(smem + asts1) = make_uint4(H[4], H[5], H[6], H[7]);
        *(uint4*)(smem + 8192 + asts0) = make_uint4(M[0], M[1], M[2], M[3]);
        *(uint4*)(smem + 8192 + asts1) = make_uint4(M[4], M[5], M[6], M[7]);
    }

    const int arow = lane & 15, asel = lane >> 4;
    const int kl = (lane & 7) + (lane & 8);
    const int bsel = lane >> 4;

    for (int s = 0; s < NSTAGES; ++s) {
        const int cur = s & 1;
        asm volatile("cp.async.wait_group 0;" ::: "memory");
        __syncthreads();

        const u32 nbase = sbase + (cur ^ 1) * STAGE_BYTES;
        if (s + 1 < NSTAGES) {
            cp16(nbase + 16384 + bswz, WhP + (size_t)(s + 1) * wstride);
            cp16(nbase + 20480 + bswz, WmP + (size_t)(s + 1) * wstride);
            asm volatile("cp.async.commit_group;" ::: "memory");
            const float* ap = Aptr + (s + 1) * BK;
#pragma unroll
            for (int i = 0; i < 4; ++i) ar[i] = *(const float4*)(ap + i * 4);
        }

        // ---- compute stage cur ----
        {
            const u32 sA = sbase + cur * STAGE_BYTES;
#pragma unroll
            for (int k16 = 0; k16 < 2; ++k16) {
                u32 fah[2][4], fam[2][4], bh[4][2], bm[4][2];
#pragma unroll
                for (int mt = 0; mt < 2; ++mt) {
                    int ml = wm * 32 + mt * 16 + arow;
                    u32 off = (u32)ml * 64 + (u32)((((k16 * 2 + asel) ^ (arow & 3))) * 16);
                    ldmA(fah[mt], sA + off);
                    ldmA(fam[mt], sA + 8192 + off);
                }
#pragma unroll
                for (int nt = 0; nt < 2; ++nt) {
                    u32 off = (u32)(k16 * 16 + kl) * 128 +
                              (u32)((((wn * 4 + nt * 2 + bsel) ^ (lane & 7))) * 16);
                    u32 r[4];
                    ldmBT(r, sA + 16384 + off);
                    bh[nt * 2][0] = r[0]; bh[nt * 2][1] = r[1];
                    bh[nt * 2 + 1][0] = r[2]; bh[nt * 2 + 1][1] = r[3];
                    ldmBT(r, sA + 20480 + off);
                    bm[nt * 2][0] = r[0]; bm[nt * 2][1] = r[1];
                    bm[nt * 2 + 1][0] = r[2]; bm[nt * 2 + 1][1] = r[3];
                }
#pragma unroll
                for (int mt = 0; mt < 2; ++mt)
#pragma unroll
                    for (int t = 0; t < 4; ++t) {
                        mma16816(chk[mt][t], fah[mt], bh[t]);   // hh
                        mma16816(chk[mt][t], fah[mt], bm[t]);   // hm
                        mma16816(chk[mt][t], fam[mt], bh[t]);   // mh
                    }
            }
        }

        // ---- stage s+1 A convert + STS ----
        if (s + 1 < NSTAGES) {
            u32 H[8], M[8];
            split16(ar, H, M);
            char* nb = smem + (cur ^ 1) * STAGE_BYTES;
            *(uint4*)(nb + asts0) = make_uint4(H[0], H[1], H[2], H[3]);
            *(uint4*)(nb + asts1) = make_uint4(H[4], H[5], H[6], H[7]);
            *(uint4*)(nb + 8192 + asts0) = make_uint4(M[0], M[1], M[2], M[3]);
            *(uint4*)(nb + 8192 + asts1) = make_uint4(M[4], M[5], M[6], M[7]);
        }

        // ---- two-level accumulation fold (every 16 stages = K 512) ----
        if ((s & 15) == 15) {
#pragma unroll
            for (int i = 0; i < 2; ++i)
#pragma unroll
                for (int j = 0; j < 4; ++j)
#pragma unroll
                    for (int q = 0; q < 4; ++q) {
                        mast[i][j][q] += chk[i][j][q];
                        chk[i][j][q] = 0.f;
                    }
        }
    }

    // ---- epilogue ----
    const int g = lane >> 2, qp = (lane & 3) * 2;
#pragma unroll
    for (int mt = 0; mt < 2; ++mt)
#pragma unroll
        for (int t = 0; t < 4; ++t) {
            int token = blockIdx.x * BLK_M + wm * 32 + mt * 16 + g;
            int e = blockIdx.y * BLK_N + wn * 32 + t * 8 + qp;
            float* p = g_logits + (size_t)token * N_EXP + e;
            *(float2*)p = make_float2(mast[mt][t][0], mast[mt][t][1]);
            *(float2*)(p + 8 * N_EXP) = make_float2(mast[mt][t][2], mast[mt][t][3]);
        }
}

// ---------------------------------------------------------------------------
// Phase 2: grouped top-k. One warp per token.
// ---------------------------------------------------------------------------
__global__ __launch_bounds__(256) void topk_kernel(
    const float* __restrict__ bias,
    float* __restrict__ out_idx,
    float* __restrict__ out_w)
{
    __shared__ float bsh[N_EXP];
    __shared__ float s_sh[8][N_EXP];

    const int tid  = threadIdx.x;
    const int warp = tid >> 5;
    const int lane = tid & 31;
    const unsigned FULL = 0xFFFFFFFFu;

    if (tid < N_EXP) bsh[tid] = bias[tid];
    __syncthreads();

    const int token = blockIdx.x * 8 + warp;
    const float* lg = g_logits + (size_t)token * N_EXP + lane * 8;

    float c[8];
#pragma unroll
    for (int j = 0; j < 8; ++j) {
        float x = lg[j];
        float sg = 1.0f / (1.0f + expf(-x));
        c[j] = sg + bsh[lane * 8 + j];
        s_sh[warp][lane * 8 + j] = sg;
    }
    __syncwarp();

    float m1 = -INFINITY, m2 = -INFINITY;
#pragma unroll
    for (int j = 0; j < 8; ++j) {
        float v = c[j];
        if (v > m1) { m2 = m1; m1 = v; }
        else if (v > m2) { m2 = v; }
    }
#pragma unroll
    for (int off = 2; off >= 1; off >>= 1) {
        float o1 = __shfl_xor_sync(FULL, m1, off);
        float o2 = __shfl_xor_sync(FULL, m2, off);
        if (o1 > m1) { m2 = fmaxf(m1, o2); m1 = o1; }
        else         { m2 = fmaxf(m2, o1); }
    }
    float gsum = m1 + m2;

    float gs[NGROUP];
#pragma unroll
    for (int g = 0; g < NGROUP; ++g) gs[g] = __shfl_sync(FULL, gsum, g * 4);

    const int myg = lane >> 2;
    const float mys = gs[myg];
    int rank = 0;
#pragma unroll
    for (int g = 0; g < NGROUP; ++g)
        rank += (gs[g] > mys) || (gs[g] == mys && g < myg);
    const bool sel = (rank < TOPKG);

    float mc[8];
#pragma unroll
    for (int j = 0; j < 8; ++j) mc[j] = sel ? c[j] : 0.0f;

    float wsum = 0.0f;
    int   myidx = 0;
    float myw   = 0.0f;
#pragma unroll
    for (int t = 0; t < TOPK; ++t) {
        float bv = -INFINITY;
        int   bi = N_EXP;
#pragma unroll
        for (int j = 0; j < 8; ++j) {
            if (mc[j] > bv) { bv = mc[j]; bi = lane * 8 + j; }
        }
#pragma unroll
        for (int off = 16; off >= 1; off >>= 1) {
            float ov = __shfl_xor_sync(FULL, bv, off);
            int   oi = __shfl_xor_sync(FULL, bi, off);
            if (ov > bv || (ov == bv && oi < bi)) { bv = ov; bi = oi; }
        }
        float sv = s_sh[warp][bi];
        wsum += sv;
        if (lane == t) { myidx = bi; myw = sv; }
        if ((bi >> 3) == lane) {
            int jj = bi & 7;
#pragma unroll
            for (int j = 0; j < 8; ++j)
                if (j == jj) mc[j] = -INFINITY;
        }
    }

    const float scale = 2.5f / (wsum + 1e-20f);
    if (lane < TOPK) {
        out_idx[(size_t)token * TOPK + lane] = (float)myidx;
        out_w  [(size_t)token * TOPK + lane] = myw * scale;
    }
}

// ---------------------------------------------------------------------------
extern "C" void kernel_launch(void* const* d_in, const int* in_sizes, int n_in,
                              void* d_out, int out_size) {
    const float* hidden = (const float*)d_in[0];   // [16384, 7168]
    const float* weight = (const float*)d_in[1];   // [256, 7168]
    const float* bias   = (const float*)d_in[2];   // [256]
    float* out = (float*)d_out;                    // [indices | weights], fp32

    w_convert<<<HID, 256>>>(weight);
    router_hmma<<<dim3(T_TOKENS / BLK_M, N_EXP / BLK_N), 256, SMEM_TOTAL>>>(hidden);
    topk_kernel<<<T_TOKENS / 8, 256>>>(bias, out, out + (size_t)T_TOKENS * TOPK);
}

// round 14
// speedup vs baseline: 2.9150x; 1.1745x over previous
#include <cuda_runtime.h>
#include <cuda_fp16.h>
#include <math.h>

#define T_TOKENS 16384
#define N_EXP    256
#define HID      7168
#define NGROUP   8
#define TOPKG    4
#define TOPK     8

#define BLK_M    128
#define BLK_N    64
#define BK       32
#define NSTAGES  224           // HID / BK
#define STAGE_BYTES 24576      // Ah 8192 | Am 8192 | Bh 4096 | Bm 4096
#define SMEM_TOTAL 49152

typedef unsigned int u32;

// static device scratch (allowed)
__device__ __half g_Wh[(size_t)HID * N_EXP];     // W transposed, high limb  [k][n]
__device__ __half g_Wm[(size_t)HID * N_EXP];     // W transposed, low  limb  [k][n]
__device__ float  g_logits[(size_t)T_TOKENS * N_EXP];

// ---------------------------------------------------------------------------
__device__ __forceinline__ u32 smem_u32(const void* p) {
    u32 r;
    asm("{ .reg .u64 t; cvta.to.shared.u64 t, %1; cvt.u32.u64 %0, t; }" : "=r"(r) : "l"(p));
    return r;
}

__device__ __forceinline__ void ldmA(u32* r, u32 addr) {
    asm volatile("ldmatrix.sync.aligned.m8n8.x4.shared.b16 {%0,%1,%2,%3}, [%4];"
                 : "=r"(r[0]), "=r"(r[1]), "=r"(r[2]), "=r"(r[3]) : "r"(addr));
}
__device__ __forceinline__ void ldmBT(u32* r, u32 addr) {
    asm volatile("ldmatrix.sync.aligned.m8n8.x4.trans.shared.b16 {%0,%1,%2,%3}, [%4];"
                 : "=r"(r[0]), "=r"(r[1]), "=r"(r[2]), "=r"(r[3]) : "r"(addr));
}
__device__ __forceinline__ void mma16816(float* c, const u32* a, const u32* b) {
    asm volatile(
        "mma.sync.aligned.m16n8k16.row.col.f32.f16.f16.f32 "
        "{%0,%1,%2,%3}, {%4,%5,%6,%7}, {%8,%9}, {%0,%1,%2,%3};"
        : "+f"(c[0]), "+f"(c[1]), "+f"(c[2]), "+f"(c[3])
        : "r"(a[0]), "r"(a[1]), "r"(a[2]), "r"(a[3]), "r"(b[0]), "r"(b[1]));
}
__device__ __forceinline__ void cp16(u32 dst, const void* src) {
    asm volatile("cp.async.cg.shared.global [%0], [%1], 16;" :: "r"(dst), "l"(src) : "memory");
}

// split 16 fp32 -> 8x u32 high-limb pairs + 8x u32 low-limb pairs
__device__ __forceinline__ void split16(const float4* v, u32* H, u32* M) {
    const float* x = (const float*)v;
#pragma unroll
    for (int i = 0; i < 8; ++i) {
        float a = x[2 * i], b = x[2 * i + 1];
        __half ha = __float2half_rn(a), hb = __float2half_rn(b);
        float ma = a - __half2float(ha);
        float mb = b - __half2float(hb);
        __half2 hh = __halves2half2(ha, hb);
        __half2 mm = __floats2half2_rn(ma, mb);
        H[i] = *(u32*)&hh;
        M[i] = *(u32*)&mm;
    }
}

// ---------------------------------------------------------------------------
// Phase 0: W -> transposed fp16 limb arrays Wt[k][n]
// ---------------------------------------------------------------------------
__global__ __launch_bounds__(256) void w_convert(const float* __restrict__ W) {
    const int k = blockIdx.x;        // 0..7167
    const int e = threadIdx.x;       // 0..255
    float x = W[(size_t)e * HID + k];
    __half h = __float2half_rn(x);
    __half m = __float2half_rn(x - __half2float(h));
    g_Wh[(size_t)k * N_EXP + e] = h;
    g_Wm[(size_t)k * N_EXP + e] = m;
}

// ---------------------------------------------------------------------------
// Phase 1: fp16x2-limb HMMA GEMM.  logits[t,e] = sum_k A[t,k] W[e,k]
// CTA 128x64, 8 warps (4m x 2n), warp 32x32, BK=32, double buffered.
// Terms: hh (+ hm + mh); two-level accumulation (fold every 16 stages).
// Occupancy 2 (4 warps/SMSP) to hide ldmatrix->mma and LDG latency.
// NOTE: per-output FP op order identical to round-7 kernel -> bit-identical
// logits -> expected rel_err exactly 4.299e-4.
// ---------------------------------------------------------------------------
__global__ __launch_bounds__(256, 2) void router_hmma(const float* __restrict__ A) {
    extern __shared__ char smem[];
    const u32 sbase = smem_u32(smem);
    const int tid = threadIdx.x, lane = tid & 31, wid = tid >> 5;
    const int wm = wid & 3, wn = wid >> 2;

    float mast[2][4][4], chk[2][4][4];
#pragma unroll
    for (int i = 0; i < 2; ++i)
#pragma unroll
        for (int j = 0; j < 4; ++j)
#pragma unroll
            for (int q = 0; q < 4; ++q) { mast[i][j][q] = 0.f; chk[i][j][q] = 0.f; }

    // A staging: thread -> (row am, 16-float half ah)
    const int am = tid >> 1;
    const int ah = tid & 1;
    const float* Aptr = A + (size_t)(blockIdx.x * BLK_M + am) * HID + ah * 16;
    const u32 asts0 = (u32)am * 64 + (u32)((((ah * 2 + 0) ^ (am & 3))) * 16);
    const u32 asts1 = (u32)am * 64 + (u32)((((ah * 2 + 1) ^ (am & 3))) * 16);

    // B staging: thread -> (k row bk, 16B chunk bnc)
    const int bk = tid >> 3;
    const int bnc = tid & 7;
    const int n0 = blockIdx.y * BLK_N;
    const __half* WhP = g_Wh + (size_t)bk * N_EXP + n0 + bnc * 8;
    const __half* WmP = g_Wm + (size_t)bk * N_EXP + n0 + bnc * 8;
    const u32 bswz = (u32)bk * 128 + (u32)((bnc ^ (bk & 7)) * 16);
    const size_t wstride = (size_t)BK * N_EXP;   // halves per stage

    // ---- prologue: stage 0 ----
    float4 ar[4];
    {
        cp16(sbase + 16384 + bswz, WhP);
        cp16(sbase + 20480 + bswz, WmP);
        asm volatile("cp.async.commit_group;" ::: "memory");
#pragma unroll
        for (int i = 0; i < 4; ++i) ar[i] = *(const float4*)(Aptr + i * 4);
        u32 H[8], M[8];
        split16(ar, H, M);
        *(uint4*)(smem + asts0) = make_uint4(H[0], H[1], H[2], H[3]);
        *(uint4*)(smem + asts1) = make_uint4(H[4], H[5], H[6], H[7]);
        *(uint4*)(smem + 8192 + asts0) = make_uint4(M[0], M[1], M[2], M[3]);
        *(uint4*)(smem + 8192 + asts1) = make_uint4(M[4], M[5], M[6], M[7]);
    }

    const int arow = lane & 15, asel = lane >> 4;
    const int kl = (lane & 7) + (lane & 8);
    const int bsel = lane >> 4;

    for (int s = 0; s < NSTAGES; ++s) {
        const int cur = s & 1;
        asm volatile("cp.async.wait_group 0;" ::: "memory");
        __syncthreads();

        const u32 nbase = sbase + (cur ^ 1) * STAGE_BYTES;
        if (s + 1 < NSTAGES) {
            cp16(nbase + 16384 + bswz, WhP + (size_t)(s + 1) * wstride);
            cp16(nbase + 20480 + bswz, WmP + (size_t)(s + 1) * wstride);
            asm volatile("cp.async.commit_group;" ::: "memory");
            const float* ap = Aptr + (s + 1) * BK;
#pragma unroll
            for (int i = 0; i < 4; ++i) ar[i] = *(const float4*)(ap + i * 4);
        }

        // ---- compute stage cur ----
        {
            const u32 sA = sbase + cur * STAGE_BYTES;
#pragma unroll
            for (int k16 = 0; k16 < 2; ++k16) {
                u32 fah[2][4], fam[2][4], bh[4][2], bm[4][2];
#pragma unroll
                for (int mt = 0; mt < 2; ++mt) {
                    int ml = wm * 32 + mt * 16 + arow;
                    u32 off = (u32)ml * 64 + (u32)((((k16 * 2 + asel) ^ (arow & 3))) * 16);
                    ldmA(fah[mt], sA + off);
                    ldmA(fam[mt], sA + 8192 + off);
                }
#pragma unroll
                for (int nt = 0; nt < 2; ++nt) {
                    u32 off = (u32)(k16 * 16 + kl) * 128 +
                              (u32)((((wn * 4 + nt * 2 + bsel) ^ (lane & 7))) * 16);
                    u32 r[4];
                    ldmBT(r, sA + 16384 + off);
                    bh[nt * 2][0] = r[0]; bh[nt * 2][1] = r[1];
                    bh[nt * 2 + 1][0] = r[2]; bh[nt * 2 + 1][1] = r[3];
                    ldmBT(r, sA + 20480 + off);
                    bm[nt * 2][0] = r[0]; bm[nt * 2][1] = r[1];
                    bm[nt * 2 + 1][0] = r[2]; bm[nt * 2 + 1][1] = r[3];
                }
#pragma unroll
                for (int mt = 0; mt < 2; ++mt)
#pragma unroll
                    for (int t = 0; t < 4; ++t) {
                        mma16816(chk[mt][t], fah[mt], bh[t]);   // hh
                        mma16816(chk[mt][t], fah[mt], bm[t]);   // hm
                        mma16816(chk[mt][t], fam[mt], bh[t]);   // mh
                    }
            }
        }

        // ---- stage s+1 A convert + STS ----
        if (s + 1 < NSTAGES) {
            u32 H[8], M[8];
            split16(ar, H, M);
            char* nb = smem + (cur ^ 1) * STAGE_BYTES;
            *(uint4*)(nb + asts0) = make_uint4(H[0], H[1], H[2], H[3]);
            *(uint4*)(nb + asts1) = make_uint4(H[4], H[5], H[6], H[7]);
            *(uint4*)(nb + 8192 + asts0) = make_uint4(M[0], M[1], M[2], M[3]);
            *(uint4*)(nb + 8192 + asts1) = make_uint4(M[4], M[5], M[6], M[7]);
        }

        // ---- two-level accumulation fold (every 16 stages = K 512) ----
        if ((s & 15) == 15) {
#pragma unroll
            for (int i = 0; i < 2; ++i)
#pragma unroll
                for (int j = 0; j < 4; ++j)
#pragma unroll
                    for (int q = 0; q < 4; ++q) {
                        mast[i][j][q] += chk[i][j][q];
                        chk[i][j][q] = 0.f;
                    }
        }
    }

    // ---- epilogue ----
    const int g = lane >> 2, qp = (lane & 3) * 2;
#pragma unroll
    for (int mt = 0; mt < 2; ++mt)
#pragma unroll
        for (int t = 0; t < 4; ++t) {
            int token = blockIdx.x * BLK_M + wm * 32 + mt * 16 + g;
            int e = blockIdx.y * BLK_N + wn * 32 + t * 8 + qp;
            float* p = g_logits + (size_t)token * N_EXP + e;
            *(float2*)p = make_float2(mast[mt][t][0], mast[mt][t][1]);
            *(float2*)(p + 8 * N_EXP) = make_float2(mast[mt][t][2], mast[mt][t][3]);
        }
}

// ---------------------------------------------------------------------------
// Phase 2: grouped top-k. One warp per token.
// ---------------------------------------------------------------------------
__global__ __launch_bounds__(256) void topk_kernel(
    const float* __restrict__ bias,
    float* __restrict__ out_idx,
    float* __restrict__ out_w)
{
    __shared__ float bsh[N_EXP];
    __shared__ float s_sh[8][N_EXP];

    const int tid  = threadIdx.x;
    const int warp = tid >> 5;
    const int lane = tid & 31;
    const unsigned FULL = 0xFFFFFFFFu;

    if (tid < N_EXP) bsh[tid] = bias[tid];
    __syncthreads();

    const int token = blockIdx.x * 8 + warp;
    const float* lg = g_logits + (size_t)token * N_EXP + lane * 8;

    float c[8];
#pragma unroll
    for (int j = 0; j < 8; ++j) {
        float x = lg[j];
        float sg = 1.0f / (1.0f + expf(-x));
        c[j] = sg + bsh[lane * 8 + j];
        s_sh[warp][lane * 8 + j] = sg;
    }
    __syncwarp();

    float m1 = -INFINITY, m2 = -INFINITY;
#pragma unroll
    for (int j = 0; j < 8; ++j) {
        float v = c[j];
        if (v > m1) { m2 = m1; m1 = v; }
        else if (v > m2) { m2 = v; }
    }
#pragma unroll
    for (int off = 2; off >= 1; off >>= 1) {
        float o1 = __shfl_xor_sync(FULL, m1, off);
        float o2 = __shfl_xor_sync(FULL, m2, off);
        if (o1 > m1) { m2 = fmaxf(m1, o2); m1 = o1; }
        else         { m2 = fmaxf(m2, o1); }
    }
    float gsum = m1 + m2;

    float gs[NGROUP];
#pragma unroll
    for (int g = 0; g < NGROUP; ++g) gs[g] = __shfl_sync(FULL, gsum, g * 4);

    const int myg = lane >> 2;
    const float mys = gs[myg];
    int rank = 0;
#pragma unroll
    for (int g = 0; g < NGROUP; ++g)
        rank += (gs[g] > mys) || (gs[g] == mys && g < myg);
    const bool sel = (rank < TOPKG);

    float mc[8];
#pragma unroll
    for (int j = 0; j < 8; ++j) mc[j] = sel ? c[j] : 0.0f;

    float wsum = 0.0f;
    int   myidx = 0;
    float myw   = 0.0f;
#pragma unroll
    for (int t = 0; t < TOPK; ++t) {
        float bv = -INFINITY;
        int   bi = N_EXP;
#pragma unroll
        for (int j = 0; j < 8; ++j) {
            if (mc[j] > bv) { bv = mc[j]; bi = lane * 8 + j; }
        }
#pragma unroll
        for (int off = 16; off >= 1; off >>= 1) {
            float ov = __shfl_xor_sync(FULL, bv, off);
            int   oi = __shfl_xor_sync(FULL, bi, off);
            if (ov > bv || (ov == bv && oi < bi)) { bv = ov; bi = oi; }
        }
        float sv = s_sh[warp][bi];
        wsum += sv;
        if (lane == t) { myidx = bi; myw = sv; }
        if ((bi >> 3) == lane) {
            int jj = bi & 7;
#pragma unroll
            for (int j = 0; j < 8; ++j)
                if (j == jj) mc[j] = -INFINITY;
        }
    }

    const float scale = 2.5f / (wsum + 1e-20f);
    if (lane < TOPK) {
        out_idx[(size_t)token * TOPK + lane] = (float)myidx;
        out_w  [(size_t)token * TOPK + lane] = myw * scale;
    }
}

// ---------------------------------------------------------------------------
extern "C" void kernel_launch(void* const* d_in, const int* in_sizes, int n_in,
                              void* d_out, int out_size) {
    const float* hidden = (const float*)d_in[0];   // [16384, 7168]
    const float* weight = (const float*)d_in[1];   // [256, 7168]
    const float* bias   = (const float*)d_in[2];   // [256]
    float* out = (float*)d_out;                    // [indices | weights], fp32

    w_convert<<<HID, 256>>>(weight);
    router_hmma<<<dim3(T_TOKENS / BLK_M, N_EXP / BLK_N), 256, SMEM_TOTAL>>>(hidden);
    topk_kernel<<<T_TOKENS / 8, 256>>>(bias, out, out + (size_t)T_TOKENS * TOPK);
}